// round 12
// baseline (speedup 1.0000x reference)
#include <cuda_runtime.h>

#define T_HOR 100
#define B_BATCH 512
#define REGU 1e-6f

typedef unsigned long long ull;

__device__ float g_K[B_BATCH * T_HOR * 8 * 24];
__device__ float g_kv[B_BATCH * T_HOR * 8];

__device__ __forceinline__ ull pack2(float s) {
    ull d; asm("mov.b64 %0, {%1, %1};" : "=l"(d) : "f"(s)); return d;
}
__device__ __forceinline__ void ffma2(ull& d, ull a, ull b) {
    asm("fma.rn.f32x2 %0, %1, %2, %0;" : "+l"(d) : "l"(a), "l"(b));
}
__device__ __forceinline__ float2 unpack2(ull v) {
    float2 r; asm("mov.b64 {%0, %1}, %2;" : "=f"(r.x), "=f"(r.y) : "l"(v)); return r;
}
__device__ __forceinline__ void cp16(unsigned sa, const void* g) {
    asm volatile("cp.async.cg.shared.global [%0], [%1], 16;" :: "r"(sa), "l"(g));
}
__device__ __forceinline__ void cp4(unsigned sa, const void* g) {
    asm volatile("cp.async.ca.shared.global [%0], [%1], 4;" :: "r"(sa), "l"(g));
}

extern "C" __global__ void __launch_bounds__(128, 4)
lqr_kernel(const float* __restrict__ d_x0,
           const float* __restrict__ d_C,
           const float* __restrict__ d_c,
           const float* __restrict__ d_Cf,
           const float* __restrict__ d_cf,
           const float* __restrict__ d_xref,
           const float* __restrict__ d_uref,
           const float* __restrict__ d_A,
           const float* __restrict__ d_B,
           float* __restrict__ d_out)
{
    __shared__ __align__(16) float sAB[24 * 36];
    __shared__ __align__(16) float sC[2][32 * 36];
    __shared__ __align__(16) float sSc[2][64];     // [0..31]=c, [32..55]=xref, [56..63]=uref
    __shared__ __align__(16) float sG[24 * 36];    // G = V·AB (loop invariant)
    __shared__ __align__(16) float sH[32 * 36];    // full H
    __shared__ __align__(16) float sK[8 * 28];
    __shared__ __align__(16) float sM[8 * 36];     // M = K·AB
    __shared__ __align__(16) float sQ[32], sv[32];
    __shared__ float skv[8];
    __shared__ float sx[24];

    const int tid = threadIdx.x;
    const int b = blockIdx.x;

    // ---------------- preamble ----------------
    for (int e = tid; e < 24 * 32; e += 128) {
        int j = e >> 5, cc = e & 31;
        sAB[j * 36 + cc] = (cc < 24) ? d_A[j * 24 + cc] : d_B[j * 8 + (cc - 24)];
    }
    // V_T = Cf[:24,:24] into sH rows 0..23
    for (int e = tid; e < 576; e += 128) {
        int i = e / 24, j = e - i * 24;
        sH[i * 36 + j] = d_Cf[(size_t)b * 1024 + i * 32 + j];
    }
    if (tid < 24) sQ[tid] = d_xref[((size_t)b * 101 + 100) * 24 + tid];
    {
        const float4* C4 = (const float4*)(d_C + ((size_t)b * T_HOR + 99) * 1024);
        #pragma unroll
        for (int ss = 0; ss < 2; ss++) {
            const int s = tid + ss * 128;
            *(float4*)(sC[0] + (s >> 3) * 36 + ((s & 7) << 2)) = C4[s];
        }
        if (tid < 32)
            sSc[0][tid] = d_c[((size_t)b * T_HOR + 99) * 32 + tid];
        else if (tid < 56)
            sSc[0][tid] = d_xref[((size_t)b * 101 + 99) * 24 + (tid - 32)];
        else if (tid < 64)
            sSc[0][tid] = d_uref[((size_t)b * T_HOR + 99) * 8 + (tid - 56)];
    }
    __syncthreads();
    // G(99) = V_T·AB (96 thr, V_T symmetric -> contiguous reads) ; v_T (tid 96..119)
    if (tid < 96) {
        const int i0 = (tid >> 3) * 2, c4 = (tid & 7) << 2;
        ull aL0 = 0, aH0 = 0, aL1 = 0, aH1 = 0;
        #pragma unroll
        for (int j = 0; j < 24; j++) {
            const float2 vv = *(const float2*)(sH + j * 36 + i0);
            const ulonglong2 ab = *(const ulonglong2*)(sAB + j * 36 + c4);
            const ull v0 = pack2(vv.x), v1 = pack2(vv.y);
            ffma2(aL0, v0, ab.x); ffma2(aH0, v0, ab.y);
            ffma2(aL1, v1, ab.x); ffma2(aH1, v1, ab.y);
        }
        *(ulonglong2*)(sG + i0 * 36 + c4)       = make_ulonglong2(aL0, aH0);
        *(ulonglong2*)(sG + (i0 + 1) * 36 + c4) = make_ulonglong2(aL1, aH1);
    } else if (tid < 120) {
        const int i = tid - 96;
        float acc = d_cf[b * 32 + i];
        #pragma unroll
        for (int j = 0; j < 24; j++) acc -= sH[i * 36 + j] * sQ[j];
        sv[i] = acc;
    }
    __syncthreads();
    // Q(99)
    if (tid < 32) {
        const int r = tid;
        float acc = sSc[0][r];
        #pragma unroll
        for (int j4 = 0; j4 < 8; j4++) {
            const float4 cr = *(const float4*)(sC[0] + r * 36 + j4 * 4);
            const float4 zz = *(const float4*)(sSc[0] + 32 + j4 * 4);
            acc -= cr.x * zz.x + cr.y * zz.y + cr.z * zz.z + cr.w * zz.w;
        }
        #pragma unroll
        for (int j = 0; j < 24; j++) acc += sAB[j * 36 + r] * sv[j];
        sQ[r] = acc;
    }
    __syncthreads();

    // ---------------- backward Riccati ----------------
    int buf = 0;
    for (int t = 99; t >= 0; --t) {
        const float* sCb = sC[buf];

        if (t > 0) {
            const float4* src = (const float4*)(d_C + ((size_t)b * T_HOR + t - 1) * 1024);
            float* dst = sC[buf ^ 1];
            #pragma unroll
            for (int ss = 0; ss < 2; ss++) {
                const int s = tid + ss * 128;
                cp16((unsigned)__cvta_generic_to_shared(dst + (s >> 3) * 36 + ((s & 7) << 2)),
                     src + s);
            }
            if (tid < 64) {
                const float* g;
                if (tid < 32)      g = d_c    + ((size_t)b * T_HOR + t - 1) * 32 + tid;
                else if (tid < 56) g = d_xref + ((size_t)b * 101 + t - 1) * 24 + (tid - 32);
                else               g = d_uref + ((size_t)b * T_HOR + t - 1) * 8 + (tid - 56);
                cp4((unsigned)__cvta_generic_to_shared(&sSc[buf ^ 1][tid]), g);
            }
            asm volatile("cp.async.commit_group;");
        }

        // ---- Ph1: H = C + ABᵀ·G, full 32x32 (+REG diag), 128 thr 2x4 f32x2
        {
            const int r0 = (tid >> 3) * 2, c4 = (tid & 7) << 2;
            const ulonglong2 c0 = *(const ulonglong2*)(sCb + r0 * 36 + c4);
            const ulonglong2 c1 = *(const ulonglong2*)(sCb + (r0 + 1) * 36 + c4);
            ull aL0 = c0.x, aH0 = c0.y, aL1 = c1.x, aH1 = c1.y;
            #pragma unroll
            for (int j = 0; j < 24; j++) {
                const float2 aa = *(const float2*)(sAB + j * 36 + r0);
                const ulonglong2 gg = *(const ulonglong2*)(sG + j * 36 + c4);
                const ull a0 = pack2(aa.x), a1 = pack2(aa.y);
                ffma2(aL0, a0, gg.x); ffma2(aH0, a0, gg.y);
                ffma2(aL1, a1, gg.x); ffma2(aH1, a1, gg.y);
            }
            float2 r0lo = unpack2(aL0), r0hi = unpack2(aH0);
            float2 r1lo = unpack2(aL1), r1hi = unpack2(aH1);
            if (r0 >= 24) {
                float v0[4] = { r0lo.x, r0lo.y, r0hi.x, r0hi.y };
                float v1[4] = { r1lo.x, r1lo.y, r1hi.x, r1hi.y };
                const int d0 = r0 - c4;
                if (d0 >= 0 && d0 < 4) v0[d0] += REGU;
                const int d1 = r0 + 1 - c4;
                if (d1 >= 0 && d1 < 4) v1[d1] += REGU;
                *(float4*)(sH + r0 * 36 + c4)       = make_float4(v0[0], v0[1], v0[2], v0[3]);
                *(float4*)(sH + (r0 + 1) * 36 + c4) = make_float4(v1[0], v1[1], v1[2], v1[3]);
            } else {
                *(float4*)(sH + r0 * 36 + c4)       = make_float4(r0lo.x, r0lo.y, r0hi.x, r0hi.y);
                *(float4*)(sH + (r0 + 1) * 36 + c4) = make_float4(r1lo.x, r1lo.y, r1hi.x, r1hi.y);
            }
        }
        __syncthreads();

        // ---- Ph2: GJ [Quu|Qux|Qu] -> K,kv (warp0) ∥ G1 = Qxx·AB -> sG (96 thr)
        if (tid < 32) {
            const int seg = tid >> 3, r = tid & 7;
            float m[9];
            if (seg == 0) {
                #pragma unroll
                for (int j = 0; j < 8; j++) m[j] = sH[(24 + r) * 36 + 24 + j];
                m[8] = sQ[24 + r];
            } else {
                const int cb = (seg - 1) * 8;
                #pragma unroll
                for (int j = 0; j < 8; j++) m[j] = sH[(24 + r) * 36 + cb + j];
                m[8] = 0.f;
            }
            #pragma unroll
            for (int cc = 0; cc < 8; cc++) {
                const float p   = __shfl_sync(0xffffffffu, m[cc], cc);
                const float inv = __fdividef(1.0f, p);
                const float f   = __shfl_sync(0xffffffffu, m[cc], r);
                const float fi  = f * inv;
                const int src = (seg << 3) | cc;
                float pr[9];
                #pragma unroll
                for (int j = 0; j < 9; j++) pr[j] = __shfl_sync(0xffffffffu, m[j], src);
                const bool isPiv = (r == cc);
                #pragma unroll
                for (int j = 0; j < 9; j++)
                    m[j] = isPiv ? (m[j] * inv) : (m[j] - fi * pr[j]);
            }
            if (seg == 0) {
                skv[r] = -m[8];
            } else {
                const int cb = (seg - 1) * 8;
                *(float4*)(sK + r * 28 + cb)     = make_float4(-m[0], -m[1], -m[2], -m[3]);
                *(float4*)(sK + r * 28 + cb + 4) = make_float4(-m[4], -m[5], -m[6], -m[7]);
            }
        } else {
            const int idx = tid - 32;
            const int i0 = (idx >> 3) * 2, c4 = (idx & 7) << 2;
            ull aL0 = 0, aH0 = 0, aL1 = 0, aH1 = 0;
            #pragma unroll
            for (int j = 0; j < 24; j++) {
                const float2 hh = *(const float2*)(sH + j * 36 + i0);   // Qxx[i0..i0+1][j] via symmetry
                const ulonglong2 ab = *(const ulonglong2*)(sAB + j * 36 + c4);
                const ull h0 = pack2(hh.x), h1 = pack2(hh.y);
                ffma2(aL0, h0, ab.x); ffma2(aH0, h0, ab.y);
                ffma2(aL1, h1, ab.x); ffma2(aH1, h1, ab.y);
            }
            *(ulonglong2*)(sG + i0 * 36 + c4)       = make_ulonglong2(aL0, aH0);
            *(ulonglong2*)(sG + (i0 + 1) * 36 + c4) = make_ulonglong2(aL1, aH1);
        }
        __syncthreads();

        // ---- Ph3: M = K·AB (64 thr) ∥ vn (64..87) ∥ g_K spill (88..103) ∥ g_kv (104..111)
        if (tid < 64) {
            const int a = tid >> 3, c4 = (tid & 7) << 2;
            ull aL = 0, aH = 0;
            #pragma unroll
            for (int j = 0; j < 24; j++) {
                const ull kr = pack2(sK[a * 28 + j]);
                const ulonglong2 ab = *(const ulonglong2*)(sAB + j * 36 + c4);
                ffma2(aL, kr, ab.x); ffma2(aH, kr, ab.y);
            }
            *(ulonglong2*)(sM + a * 36 + c4) = make_ulonglong2(aL, aH);
        } else if (tid < 88) {
            const int i = tid - 64;
            float acc = sQ[i];
            #pragma unroll
            for (int a = 0; a < 8; a++) acc += sH[(24 + a) * 36 + i] * skv[a];
            sv[i] = acc;
        } else if (tid < 104) {
            const int i = tid - 88;
            const int row = i >> 1, cb = (i & 1) * 12;
            const float4 a0 = *(const float4*)(sK + row * 28 + cb);
            const float4 a1 = *(const float4*)(sK + row * 28 + cb + 4);
            const float4 a2 = *(const float4*)(sK + row * 28 + cb + 8);
            float* gk = g_K + (size_t)(b * T_HOR + t) * 192 + row * 24 + cb;
            *(float4*)(gk)     = a0;
            *(float4*)(gk + 4) = a1;
            *(float4*)(gk + 8) = a2;
        } else if (tid < 112) {
            g_kv[(size_t)(b * T_HOR + t) * 8 + (tid - 104)] = skv[tid - 104];
        }
        if (t > 0) asm volatile("cp.async.wait_group 0;" ::: "memory");
        __syncthreads();

        // ---- Ph4: G += Quxᵀ·M (96 thr, 8-iter) ∥ Q(t-1) (96..127, prefetched C)
        if (tid < 96) {
            const int i0 = (tid >> 3) * 2, c4 = (tid & 7) << 2;
            ulonglong2 g0 = *(ulonglong2*)(sG + i0 * 36 + c4);
            ulonglong2 g1 = *(ulonglong2*)(sG + (i0 + 1) * 36 + c4);
            #pragma unroll
            for (int a = 0; a < 8; a++) {
                const float2 qx = *(const float2*)(sH + (24 + a) * 36 + i0);
                const ulonglong2 mm = *(const ulonglong2*)(sM + a * 36 + c4);
                const ull q0 = pack2(qx.x), q1 = pack2(qx.y);
                ffma2(g0.x, q0, mm.x); ffma2(g0.y, q0, mm.y);
                ffma2(g1.x, q1, mm.x); ffma2(g1.y, q1, mm.y);
            }
            *(ulonglong2*)(sG + i0 * 36 + c4)       = g0;
            *(ulonglong2*)(sG + (i0 + 1) * 36 + c4) = g1;
        } else if (t > 0) {
            const int r = tid - 96;
            const float* sCN  = sC[buf ^ 1];
            const float* sScN = sSc[buf ^ 1];
            float acc = sScN[r];
            #pragma unroll
            for (int j4 = 0; j4 < 8; j4++) {
                const float4 cr = *(const float4*)(sCN + r * 36 + j4 * 4);
                const float4 zz = *(const float4*)(sScN + 32 + j4 * 4);
                acc -= cr.x * zz.x + cr.y * zz.y + cr.z * zz.z + cr.w * zz.w;
            }
            #pragma unroll
            for (int j = 0; j < 24; j++) acc += sAB[j * 36 + r] * sv[j];
            sQ[r] = acc;
        }
        __syncthreads();
        buf ^= 1;
    }

    // ---------------- forward rollout: warp 0 only ----------------
    if (tid >= 32) return;
    const int lane = tid;
    float* ob = d_out + (size_t)b * 3224;

    float* sAB2 = sG;  // bank-conflict-free [A|B]: stride 33
    for (int e = lane; e < 768; e += 32) {
        const int i = e >> 5, c = e & 31;
        sAB2[i * 33 + c] = sAB[i * 36 + c];
    }
    if (lane < 24) {
        const float xi = d_x0[b * 24 + lane];
        sx[lane] = xi;
        ob[lane] = xi;
    }
    float kc[24], kn[24], kvc = 0.f, kvn = 0.f;
    if (lane < 8) {
        const float* gk = g_K + (size_t)b * T_HOR * 192 + lane * 24;
        #pragma unroll
        for (int q = 0; q < 6; q++) {
            const float4 v = *(const float4*)(gk + q * 4);
            kc[q * 4 + 0] = v.x; kc[q * 4 + 1] = v.y;
            kc[q * 4 + 2] = v.z; kc[q * 4 + 3] = v.w;
        }
        kvc = g_kv[(size_t)b * T_HOR * 8 + lane];
    }
    __syncwarp();

    for (int t = 0; t < T_HOR; t++) {
        if (lane < 8 && t + 1 < T_HOR) {
            const float* gk = g_K + (size_t)(b * T_HOR + t + 1) * 192 + lane * 24;
            #pragma unroll
            for (int q = 0; q < 6; q++) {
                const float4 v = *(const float4*)(gk + q * 4);
                kn[q * 4 + 0] = v.x; kn[q * 4 + 1] = v.y;
                kn[q * 4 + 2] = v.z; kn[q * 4 + 3] = v.w;
            }
            kvn = g_kv[(size_t)(b * T_HOR + t + 1) * 8 + lane];
        }
        float u = 0.f;
        if (lane < 8) {
            u = kvc;
            #pragma unroll
            for (int j = 0; j < 24; j++) u += kc[j] * sx[j];
            ob[2424 + t * 8 + lane] = u;
        }
        float acc = 0.f;
        {
            float ua[8];
            #pragma unroll
            for (int a = 0; a < 8; a++) ua[a] = __shfl_sync(0xffffffffu, u, a);
            if (lane < 24) {
                #pragma unroll
                for (int j = 0; j < 24; j++) acc += sAB2[lane * 33 + j] * sx[j];
                #pragma unroll
                for (int a = 0; a < 8; a++) acc += sAB2[lane * 33 + 24 + a] * ua[a];
            }
        }
        __syncwarp();
        if (lane < 24) {
            sx[lane] = acc;
            ob[(t + 1) * 24 + lane] = acc;
        }
        if (lane < 8) {
            #pragma unroll
            for (int q = 0; q < 24; q++) kc[q] = kn[q];
            kvc = kvn;
        }
        __syncwarp();
    }
}

extern "C" void kernel_launch(void* const* d_in, const int* in_sizes, int n_in,
                              void* d_out, int out_size)
{
    const float* x0   = (const float*)d_in[0];
    const float* C    = (const float*)d_in[1];
    const float* c    = (const float*)d_in[2];
    const float* Cf   = (const float*)d_in[3];
    const float* cf   = (const float*)d_in[4];
    const float* xref = (const float*)d_in[5];
    const float* uref = (const float*)d_in[6];
    const float* A    = (const float*)d_in[7];
    const float* B    = (const float*)d_in[8];

    lqr_kernel<<<B_BATCH, 128>>>(x0, C, c, Cf, cf, xref, uref, A, B, (float*)d_out);
}

// round 13
// speedup vs baseline: 1.0627x; 1.0627x over previous
#include <cuda_runtime.h>

#define T_HOR 100
#define B_BATCH 512
#define REGU 1e-6f

typedef unsigned long long ull;

__device__ float g_K[B_BATCH * T_HOR * 8 * 24];
__device__ float g_kv[B_BATCH * T_HOR * 8];

__device__ __forceinline__ ull pack2(float s) {
    ull d; asm("mov.b64 %0, {%1, %1};" : "=l"(d) : "f"(s)); return d;
}
__device__ __forceinline__ void ffma2(ull& d, ull a, ull b) {
    asm("fma.rn.f32x2 %0, %1, %2, %0;" : "+l"(d) : "l"(a), "l"(b));
}
__device__ __forceinline__ float2 unpack2(ull v) {
    float2 r; asm("mov.b64 {%0, %1}, %2;" : "=f"(r.x), "=f"(r.y) : "l"(v)); return r;
}
__device__ __forceinline__ void bulk_ld(unsigned dst, const void* src, unsigned bytes, unsigned mbar) {
    asm volatile(
        "cp.async.bulk.shared::cluster.global.mbarrier::complete_tx::bytes [%0], [%1], %2, [%3];"
        :: "r"(dst), "l"(src), "r"(bytes), "r"(mbar) : "memory");
}

extern "C" __global__ void __launch_bounds__(128, 4)
lqr_kernel(const float* __restrict__ d_x0,
           const float* __restrict__ d_C,
           const float* __restrict__ d_c,
           const float* __restrict__ d_Cf,
           const float* __restrict__ d_cf,
           const float* __restrict__ d_xref,
           const float* __restrict__ d_uref,
           const float* __restrict__ d_A,
           const float* __restrict__ d_B,
           float* __restrict__ d_out)
{
    __shared__ __align__(16) float sAB[24 * 36];
    __shared__ __align__(16) float sV[24 * 28];
    __shared__ __align__(16) float sC[2][32 * 32];   // linear rows (TMA-friendly)
    __shared__ __align__(16) float sSc[2][64];       // [0..31]=c, [32..55]=xref, [56..63]=uref
    __shared__ __align__(16) float sG[24 * 36];
    __shared__ __align__(16) float sH[32 * 36];
    __shared__ __align__(16) float sK[8 * 28];
    __shared__ __align__(16) float sQ[32], sv[32];
    __shared__ float skv[8];
    __shared__ float sx[24];
    __shared__ __align__(8) ull mbar;

    const int tid = threadIdx.x;
    const int b = blockIdx.x;
    const unsigned mba = (unsigned)__cvta_generic_to_shared(&mbar);

    // stage E map: tid>>1 over 21 lower tiles (6x6)
    int e_ti = 0, e_tk = 0;
    {
        const int tt = tid >> 1;
        int s = 0;
        #pragma unroll
        for (int i = 0; i < 6; i++) {
            if (tt >= s && tt < s + i + 1) { e_ti = i; e_tk = tt - s; }
            s += i + 1;
        }
    }
    // stage C Qxx map: (tid-32)>>1 over 21 lower tiles, valid tid 32..73
    int c_bi = 0, c_bk = 0;
    {
        const int tt = (tid - 32) >> 1;
        int s = 0;
        #pragma unroll
        for (int i = 0; i < 6; i++) {
            if (tt >= s && tt < s + i + 1) { c_bi = i; c_bk = tt - s; }
            s += i + 1;
        }
    }
    // stage B1 map (tid<60): 15 tiles (Qux 12 + Quu 3), 1 row x 4 cols
    int b1_r = 24, b1_k0 = 24;
    {
        const int tile = tid >> 2, rowin = tid & 3;
        if (tile < 6)        { b1_r = 24 + rowin; b1_k0 = tile * 4; }
        else if (tile < 12)  { b1_r = 28 + rowin; b1_k0 = (tile - 6) * 4; }
        else if (tile == 12) { b1_r = 24 + rowin; b1_k0 = 24; }
        else if (tile == 13) { b1_r = 28 + rowin; b1_k0 = 24; }
        else                 { b1_r = 28 + rowin; b1_k0 = 28; }
    }

    // ---------------- preamble ----------------
    if (tid == 0)
        asm volatile("mbarrier.init.shared.b64 [%0], 1;" :: "r"(mba) : "memory");
    for (int e = tid; e < 24 * 32; e += 128) {
        int j = e >> 5, cc = e & 31;
        sAB[j * 36 + cc] = (cc < 24) ? d_A[j * 24 + cc] : d_B[j * 8 + (cc - 24)];
    }
    for (int e = tid; e < 576; e += 128) {
        int i = e / 24, j = e - i * 24;
        sV[i * 28 + j] = d_Cf[(size_t)b * 1024 + i * 32 + j];
    }
    if (tid < 24) sQ[tid] = d_xref[((size_t)b * 101 + 100) * 24 + tid];
    {
        const float4* C4 = (const float4*)(d_C + ((size_t)b * T_HOR + 99) * 1024);
        ((float4*)sC[0])[tid]       = C4[tid];
        ((float4*)sC[0])[tid + 128] = C4[tid + 128];
        if (tid < 32)
            sSc[0][tid] = d_c[((size_t)b * T_HOR + 99) * 32 + tid];
        else if (tid < 56)
            sSc[0][tid] = d_xref[((size_t)b * 101 + 99) * 24 + (tid - 32)];
        else if (tid < 64)
            sSc[0][tid] = d_uref[((size_t)b * T_HOR + 99) * 8 + (tid - 56)];
    }
    __syncthreads();
    if (tid < 24) {
        float acc = d_cf[b * 32 + tid];
        #pragma unroll
        for (int j = 0; j < 24; j++) acc -= sV[tid * 28 + j] * sQ[j];
        sv[tid] = acc;
    }
    __syncthreads();

    // ---------------- backward Riccati ----------------
    int buf = 0, ph = 0;
    for (int t = 99; t >= 0; --t) {
        const float* sCb  = sC[buf];
        const float* sScb = sSc[buf];

        // TMA bulk prefetch of t-1 (one thread, off the LSU path)
        if (t > 0 && tid == 0) {
            asm volatile("mbarrier.arrive.expect_tx.shared.b64 _, [%0], %1;"
                         :: "r"(mba), "r"(4352u) : "memory");
            float* dst = sC[buf ^ 1];
            float* dsc = sSc[buf ^ 1];
            bulk_ld((unsigned)__cvta_generic_to_shared(dst),
                    d_C + ((size_t)b * T_HOR + t - 1) * 1024, 4096u, mba);
            bulk_ld((unsigned)__cvta_generic_to_shared(dsc),
                    d_c + ((size_t)b * T_HOR + t - 1) * 32, 128u, mba);
            bulk_ld((unsigned)__cvta_generic_to_shared(dsc + 32),
                    d_xref + ((size_t)b * 101 + t - 1) * 24, 96u, mba);
            bulk_ld((unsigned)__cvta_generic_to_shared(dsc + 56),
                    d_uref + ((size_t)b * T_HOR + t - 1) * 8, 32u, mba);
        }

        // ---- stage A: G = V*[A|B] (96 thr, 2x4, f32x2) ; Q = [Qx|Qu] (32 thr)
        if (tid < 96) {
            const int i0 = (tid >> 3) * 2, c4 = (tid & 7) << 2;
            ull aL0 = 0, aH0 = 0, aL1 = 0, aH1 = 0;
            #pragma unroll
            for (int j = 0; j < 24; j++) {
                const float2 vv = *(const float2*)(sV + j * 28 + i0);
                const ulonglong2 ab = *(const ulonglong2*)(sAB + j * 36 + c4);
                const ull v0 = pack2(vv.x), v1 = pack2(vv.y);
                ffma2(aL0, v0, ab.x); ffma2(aH0, v0, ab.y);
                ffma2(aL1, v1, ab.x); ffma2(aH1, v1, ab.y);
            }
            *(ulonglong2*)(sG + i0 * 36 + c4)       = make_ulonglong2(aL0, aH0);
            *(ulonglong2*)(sG + (i0 + 1) * 36 + c4) = make_ulonglong2(aL1, aH1);
        } else {
            const int r = tid - 96;
            float acc = sScb[r];
            #pragma unroll
            for (int j4 = 0; j4 < 8; j4++) {
                const float4 cr = *(const float4*)(sCb + r * 32 + j4 * 4);
                const float4 zz = *(const float4*)(sScb + 32 + j4 * 4);
                acc -= cr.x * zz.x + cr.y * zz.y + cr.z * zz.z + cr.w * zz.w;
            }
            #pragma unroll
            for (int j = 0; j < 24; j++) acc += sAB[j * 36 + r] * sv[j];
            sQ[r] = acc;
        }
        __syncthreads();

        // ---- stage B1: Quu + Qux only (15 tiles, 60 thr, 1x4, f32x2)
        if (tid < 60) {
            const int r = b1_r, k0 = b1_k0;
            const ulonglong2 c2 = *(const ulonglong2*)(sCb + r * 32 + k0);
            ull aL = c2.x, aH = c2.y;
            #pragma unroll
            for (int j = 0; j < 24; j++) {
                const ull ar = pack2(sAB[j * 36 + r]);
                const ulonglong2 gg = *(const ulonglong2*)(sG + j * 36 + k0);
                ffma2(aL, ar, gg.x); ffma2(aH, ar, gg.y);
            }
            const float2 lo = unpack2(aL), hi = unpack2(aH);
            float v[4] = { lo.x, lo.y, hi.x, hi.y };
            const int d = r - k0;
            if (d >= 0 && d < 4) v[d] += REGU;
            *(float4*)(sH + r * 36 + k0) = make_float4(v[0], v[1], v[2], v[3]);
        }
        __syncthreads();

        // ---- stage C: warp0 augmented GJ [Quu|Qux|Qu] -> K, kv
        //      threads 32..73: Qxx (21 lower tiles, 2x4, f32x2)
        if (tid < 32) {
            const int seg = tid >> 3, r = tid & 7;
            float m[9];
            if (seg == 0) {
                #pragma unroll
                for (int j = 0; j < 8; j++)
                    m[j] = (j <= r) ? sH[(24 + r) * 36 + 24 + j]
                                    : sH[(24 + j) * 36 + 24 + r];
                m[8] = sQ[24 + r];
            } else {
                const int cb = (seg - 1) * 8;
                #pragma unroll
                for (int j = 0; j < 8; j++)
                    m[j] = sH[(24 + r) * 36 + cb + j];
                m[8] = 0.f;
            }
            #pragma unroll
            for (int cc = 0; cc < 8; cc++) {
                const float p   = __shfl_sync(0xffffffffu, m[cc], cc);
                const float inv = __fdividef(1.0f, p);
                const float f   = __shfl_sync(0xffffffffu, m[cc], r);
                const float fi  = f * inv;
                const int src = (seg << 3) | cc;
                float pr[9];
                #pragma unroll
                for (int j = 0; j < 9; j++) pr[j] = __shfl_sync(0xffffffffu, m[j], src);
                const bool isPiv = (r == cc);
                #pragma unroll
                for (int j = 0; j < 9; j++)
                    m[j] = isPiv ? (m[j] * inv) : (m[j] - fi * pr[j]);
            }
            if (seg == 0) {
                skv[r] = -m[8];
            } else {
                const int cb = (seg - 1) * 8;
                *(float4*)(sK + r * 28 + cb)     = make_float4(-m[0], -m[1], -m[2], -m[3]);
                *(float4*)(sK + r * 28 + cb + 4) = make_float4(-m[4], -m[5], -m[6], -m[7]);
            }
        } else if (tid < 74) {
            const int r0 = c_bi * 4 + ((tid - 32) & 1) * 2;
            const int k0 = c_bk * 4;
            const ulonglong2 c0 = *(const ulonglong2*)(sCb + r0 * 32 + k0);
            const ulonglong2 c1 = *(const ulonglong2*)(sCb + (r0 + 1) * 32 + k0);
            ull aL0 = c0.x, aH0 = c0.y, aL1 = c1.x, aH1 = c1.y;
            #pragma unroll
            for (int j = 0; j < 24; j++) {
                const float2 aa = *(const float2*)(sAB + j * 36 + r0);
                const ulonglong2 gg = *(const ulonglong2*)(sG + j * 36 + k0);
                const ull a0 = pack2(aa.x), a1 = pack2(aa.y);
                ffma2(aL0, a0, gg.x); ffma2(aH0, a0, gg.y);
                ffma2(aL1, a1, gg.x); ffma2(aH1, a1, gg.y);
            }
            *(ulonglong2*)(sH + r0 * 36 + k0)       = make_ulonglong2(aL0, aH0);
            *(ulonglong2*)(sH + (r0 + 1) * 36 + k0) = make_ulonglong2(aL1, aH1);
        }
        __syncthreads();

        // ---- stage E: V tiles (0..41) ; g_K spill (74..89) ; g_kv (90..97) ; vn (100..123)
        if (tid < 42) {
            const int i0 = 4 * e_ti, k0 = 4 * e_tk;
            const int rh = i0 + (tid & 1) * 2;
            ull sL0 = 0, sH0 = 0, sL1 = 0, sH1 = 0;
            #pragma unroll
            for (int a = 0; a < 8; a++) {
                const float2 hi = *(const float2*)(sH + (24 + a) * 36 + rh);
                const ulonglong2 kk = *(const ulonglong2*)(sK + a * 28 + k0);
                const ull h0 = pack2(hi.x), h1 = pack2(hi.y);
                ffma2(sL0, h0, kk.x); ffma2(sH0, h0, kk.y);
                ffma2(sL1, h1, kk.x); ffma2(sH1, h1, kk.y);
            }
            const float2 s0a = unpack2(sL0), s0b = unpack2(sH0);
            const float2 s1a = unpack2(sL1), s1b = unpack2(sH1);
            const float S0[4] = { s0a.x, s0a.y, s0b.x, s0b.y };
            const float S1[4] = { s1a.x, s1a.y, s1b.x, s1b.y };
            const float4 h40 = *(const float4*)(sH + rh * 36 + k0);
            const float4 h41 = *(const float4*)(sH + (rh + 1) * 36 + k0);
            float v0[4], v1[4];
            #pragma unroll
            for (int c = 0; c < 4; c++) {
                v0[c] = (&h40.x)[c] + S0[c];
                v1[c] = (&h41.x)[c] + S1[c];
            }
            *(float4*)(sV + rh * 28 + k0)       = make_float4(v0[0], v0[1], v0[2], v0[3]);
            *(float4*)(sV + (rh + 1) * 28 + k0) = make_float4(v1[0], v1[1], v1[2], v1[3]);
            if (e_ti != e_tk) {
                #pragma unroll
                for (int c = 0; c < 4; c++) {
                    sV[(k0 + c) * 28 + rh]     = v0[c];
                    sV[(k0 + c) * 28 + rh + 1] = v1[c];
                }
            }
        } else if (tid >= 74 && tid < 90) {
            const int i = tid - 74;
            const int row = i >> 1, cb = (i & 1) * 12;
            const float4 a0 = *(const float4*)(sK + row * 28 + cb);
            const float4 a1 = *(const float4*)(sK + row * 28 + cb + 4);
            const float4 a2 = *(const float4*)(sK + row * 28 + cb + 8);
            float* gk = g_K + (size_t)(b * T_HOR + t) * 192 + row * 24 + cb;
            *(float4*)(gk)     = a0;
            *(float4*)(gk + 4) = a1;
            *(float4*)(gk + 8) = a2;
        } else if (tid >= 90 && tid < 98) {
            g_kv[(size_t)(b * T_HOR + t) * 8 + (tid - 90)] = skv[tid - 90];
        } else if (tid >= 100 && tid < 124) {
            const int i = tid - 100;
            float acc = sQ[i];
            #pragma unroll
            for (int a = 0; a < 8; a++) acc += sH[(24 + a) * 36 + i] * skv[a];
            sv[i] = acc;
        }
        if (t > 0) {
            asm volatile(
                "{\n\t"
                ".reg .pred P1;\n\t"
                "WAIT_%=:\n\t"
                "mbarrier.try_wait.parity.acquire.cta.shared::cta.b64 P1, [%0], %1;\n\t"
                "@P1 bra.uni DONE_%=;\n\t"
                "bra.uni WAIT_%=;\n\t"
                "DONE_%=:\n\t"
                "}" :: "r"(mba), "r"((unsigned)ph) : "memory");
            ph ^= 1;
        }
        __syncthreads();
        buf ^= 1;
    }

    // ---------------- forward rollout: warp 0 only ----------------
    if (tid >= 32) return;
    const int lane = tid;
    float* ob = d_out + (size_t)b * 3224;

    float* sAB2 = sG;  // bank-conflict-free [A|B]: stride 33
    for (int e = lane; e < 768; e += 32) {
        const int i = e >> 5, c = e & 31;
        sAB2[i * 33 + c] = sAB[i * 36 + c];
    }
    if (lane < 24) {
        const float xi = d_x0[b * 24 + lane];
        sx[lane] = xi;
        ob[lane] = xi;
    }
    float kc[24], kn[24], kvc = 0.f, kvn = 0.f;
    if (lane < 8) {
        const float* gk = g_K + (size_t)b * T_HOR * 192 + lane * 24;
        #pragma unroll
        for (int q = 0; q < 6; q++) {
            const float4 v = *(const float4*)(gk + q * 4);
            kc[q * 4 + 0] = v.x; kc[q * 4 + 1] = v.y;
            kc[q * 4 + 2] = v.z; kc[q * 4 + 3] = v.w;
        }
        kvc = g_kv[(size_t)b * T_HOR * 8 + lane];
    }
    __syncwarp();

    for (int t = 0; t < T_HOR; t++) {
        if (lane < 8 && t + 1 < T_HOR) {
            const float* gk = g_K + (size_t)(b * T_HOR + t + 1) * 192 + lane * 24;
            #pragma unroll
            for (int q = 0; q < 6; q++) {
                const float4 v = *(const float4*)(gk + q * 4);
                kn[q * 4 + 0] = v.x; kn[q * 4 + 1] = v.y;
                kn[q * 4 + 2] = v.z; kn[q * 4 + 3] = v.w;
            }
            kvn = g_kv[(size_t)(b * T_HOR + t + 1) * 8 + lane];
        }
        // u = K x + kv (lanes 0..7, two partial chains)
        float u = 0.f;
        if (lane < 8) {
            float u0 = kvc, u1 = 0.f;
            #pragma unroll
            for (int j = 0; j < 12; j++) {
                u0 += kc[j] * sx[j];
                u1 += kc[j + 12] * sx[j + 12];
            }
            u = u0 + u1;
            ob[2424 + t * 8 + lane] = u;
        }
        // broadcast u, x' = A x + B u (lanes 0..23, four partial chains)
        float acc = 0.f;
        {
            float ua[8];
            #pragma unroll
            for (int a = 0; a < 8; a++) ua[a] = __shfl_sync(0xffffffffu, u, a);
            if (lane < 24) {
                float a0 = 0.f, a1 = 0.f, a2 = 0.f, a3 = 0.f;
                #pragma unroll
                for (int j = 0; j < 8; j++) {
                    a0 += sAB2[lane * 33 + j]      * sx[j];
                    a1 += sAB2[lane * 33 + 8 + j]  * sx[8 + j];
                    a2 += sAB2[lane * 33 + 16 + j] * sx[16 + j];
                    a3 += sAB2[lane * 33 + 24 + j] * ua[j];
                }
                acc = (a0 + a1) + (a2 + a3);
            }
        }
        __syncwarp();
        if (lane < 24) {
            sx[lane] = acc;
            ob[(t + 1) * 24 + lane] = acc;
        }
        if (lane < 8) {
            #pragma unroll
            for (int q = 0; q < 24; q++) kc[q] = kn[q];
            kvc = kvn;
        }
        __syncwarp();
    }
}

extern "C" void kernel_launch(void* const* d_in, const int* in_sizes, int n_in,
                              void* d_out, int out_size)
{
    const float* x0   = (const float*)d_in[0];
    const float* C    = (const float*)d_in[1];
    const float* c    = (const float*)d_in[2];
    const float* Cf   = (const float*)d_in[3];
    const float* cf   = (const float*)d_in[4];
    const float* xref = (const float*)d_in[5];
    const float* uref = (const float*)d_in[6];
    const float* A    = (const float*)d_in[7];
    const float* B    = (const float*)d_in[8];

    lqr_kernel<<<B_BATCH, 128>>>(x0, C, c, Cf, cf, xref, uref, A, B, (float*)d_out);
}

// round 17
// speedup vs baseline: 1.1152x; 1.0494x over previous
#include <cuda_runtime.h>

#define T_HOR 100
#define B_BATCH 512
#define REGU 1e-6f

typedef unsigned long long ull;

__device__ float g_K[B_BATCH * T_HOR * 8 * 24];
__device__ float g_kv[B_BATCH * T_HOR * 8];

__device__ __forceinline__ ull pack2(float s) {
    ull d; asm("mov.b64 %0, {%1, %1};" : "=l"(d) : "f"(s)); return d;
}
__device__ __forceinline__ void ffma2(ull& d, ull a, ull b) {
    asm("fma.rn.f32x2 %0, %1, %2, %0;" : "+l"(d) : "l"(a), "l"(b));
}
__device__ __forceinline__ float2 unpack2(ull v) {
    float2 r; asm("mov.b64 {%0, %1}, %2;" : "=f"(r.x), "=f"(r.y) : "l"(v)); return r;
}
__device__ __forceinline__ void cp16(unsigned sa, const void* g) {
    asm volatile("cp.async.cg.shared.global [%0], [%1], 16;" :: "r"(sa), "l"(g));
}
__device__ __forceinline__ void cp4(unsigned sa, const void* g) {
    asm volatile("cp.async.ca.shared.global [%0], [%1], 4;" :: "r"(sa), "l"(g));
}

extern "C" __global__ void __launch_bounds__(128, 4)
lqr_kernel(const float* __restrict__ d_x0,
           const float* __restrict__ d_C,
           const float* __restrict__ d_c,
           const float* __restrict__ d_Cf,
           const float* __restrict__ d_cf,
           const float* __restrict__ d_xref,
           const float* __restrict__ d_uref,
           const float* __restrict__ d_A,
           const float* __restrict__ d_B,
           float* __restrict__ d_out)
{
    __shared__ __align__(16) float sAB[24 * 36];    // [A|B] scalar
    __shared__ __align__(16) float sABd[24 * 64];   // [A|B] duplicated pairs
    __shared__ __align__(16) float sVd[24 * 48];    // V duplicated pairs (symmetric)
    __shared__ __align__(16) float sC[2][32 * 36];
    __shared__ __align__(16) float sSc[2][64];      // [0..31]=c, [32..55]=xref, [56..63]=uref
    __shared__ __align__(16) float sG[24 * 36];
    __shared__ __align__(16) float sH[32 * 36];
    __shared__ __align__(16) float sK[8 * 28];
    __shared__ __align__(16) float sQ[32], sv[32];
    __shared__ float skv[8];
    __shared__ float sx[24];

    const int tid = threadIdx.x;
    const int b = blockIdx.x;

    // stage E map: tid>>1 over 21 lower tiles (6x6)
    int e_ti = 0, e_tk = 0;
    {
        const int tt = tid >> 1;
        int s = 0;
        #pragma unroll
        for (int i = 0; i < 6; i++) {
            if (tt >= s && tt < s + i + 1) { e_ti = i; e_tk = tt - s; }
            s += i + 1;
        }
    }
    // stage C Qxx map: (tid-32)>>1 over 21 lower tiles, valid tid 32..73
    int c_bi = 0, c_bk = 0;
    {
        const int tt = (tid - 32) >> 1;
        int s = 0;
        #pragma unroll
        for (int i = 0; i < 6; i++) {
            if (tt >= s && tt < s + i + 1) { c_bi = i; c_bk = tt - s; }
            s += i + 1;
        }
    }
    // stage B1 map (tid<60): 15 tiles (Qux 12 + Quu 3), 1 row x 4 cols
    int b1_r = 24, b1_k0 = 24;
    {
        const int tile = tid >> 2, rowin = tid & 3;
        if (tile < 6)        { b1_r = 24 + rowin; b1_k0 = tile * 4; }
        else if (tile < 12)  { b1_r = 28 + rowin; b1_k0 = (tile - 6) * 4; }
        else if (tile == 12) { b1_r = 24 + rowin; b1_k0 = 24; }
        else if (tile == 13) { b1_r = 28 + rowin; b1_k0 = 24; }
        else                 { b1_r = 28 + rowin; b1_k0 = 28; }
    }

    // ---------------- preamble ----------------
    for (int e = tid; e < 24 * 32; e += 128) {
        int j = e >> 5, cc = e & 31;
        const float val = (cc < 24) ? d_A[j * 24 + cc] : d_B[j * 8 + (cc - 24)];
        sAB[j * 36 + cc] = val;
        sABd[j * 64 + 2 * cc]     = val;
        sABd[j * 64 + 2 * cc + 1] = val;
    }
    for (int e = tid; e < 576; e += 128) {
        int i = e / 24, j = e - i * 24;
        const float v = d_Cf[(size_t)b * 1024 + i * 32 + j];
        sVd[i * 48 + 2 * j]     = v;
        sVd[i * 48 + 2 * j + 1] = v;
    }
    if (tid < 24) sQ[tid] = d_xref[((size_t)b * 101 + 100) * 24 + tid];
    {
        const float4* C4 = (const float4*)(d_C + ((size_t)b * T_HOR + 99) * 1024);
        #pragma unroll
        for (int ss = 0; ss < 2; ss++) {
            const int s = tid + ss * 128;
            *(float4*)(sC[0] + (s >> 3) * 36 + ((s & 7) << 2)) = C4[s];
        }
        if (tid < 32)
            sSc[0][tid] = d_c[((size_t)b * T_HOR + 99) * 32 + tid];
        else if (tid < 56)
            sSc[0][tid] = d_xref[((size_t)b * 101 + 99) * 24 + (tid - 32)];
        else if (tid < 64)
            sSc[0][tid] = d_uref[((size_t)b * T_HOR + 99) * 8 + (tid - 56)];
    }
    __syncthreads();
    if (tid < 24) {
        float acc = d_cf[b * 32 + tid];
        #pragma unroll
        for (int j = 0; j < 24; j++) acc -= sVd[tid * 48 + 2 * j] * sQ[j];
        sv[tid] = acc;
    }
    __syncthreads();

    // ---------------- backward Riccati ----------------
    int buf = 0;
    for (int t = 99; t >= 0; --t) {
        const float* sCb  = sC[buf];
        const float* sScb = sSc[buf];

        if (t > 0) {
            const float4* src = (const float4*)(d_C + ((size_t)b * T_HOR + t - 1) * 1024);
            float* dst = sC[buf ^ 1];
            #pragma unroll
            for (int ss = 0; ss < 2; ss++) {
                const int s = tid + ss * 128;
                cp16((unsigned)__cvta_generic_to_shared(dst + (s >> 3) * 36 + ((s & 7) << 2)),
                     src + s);
            }
            if (tid < 64) {
                const float* g;
                if (tid < 32)      g = d_c    + ((size_t)b * T_HOR + t - 1) * 32 + tid;
                else if (tid < 56) g = d_xref + ((size_t)b * 101 + t - 1) * 24 + (tid - 32);
                else               g = d_uref + ((size_t)b * T_HOR + t - 1) * 8 + (tid - 56);
                cp4((unsigned)__cvta_generic_to_shared(&sSc[buf ^ 1][tid]), g);
            }
            asm volatile("cp.async.commit_group;");
        }

        // ---- stage A: G = V*[A|B] (96 thr, 2x4, dup-V loads) ; Q = [Qx|Qu] (32 thr)
        if (tid < 96) {
            const int i0 = (tid >> 3) * 2, c4 = (tid & 7) << 2;
            ull aL0 = 0, aH0 = 0, aL1 = 0, aH1 = 0;
            #pragma unroll
            for (int j = 0; j < 24; j++) {
                const ulonglong2 vv2 = *(const ulonglong2*)(sVd + j * 48 + i0 * 2); // (v0,v0,v1,v1)
                const ulonglong2 ab  = *(const ulonglong2*)(sAB + j * 36 + c4);
                ffma2(aL0, vv2.x, ab.x); ffma2(aH0, vv2.x, ab.y);
                ffma2(aL1, vv2.y, ab.x); ffma2(aH1, vv2.y, ab.y);
            }
            *(ulonglong2*)(sG + i0 * 36 + c4)       = make_ulonglong2(aL0, aH0);
            *(ulonglong2*)(sG + (i0 + 1) * 36 + c4) = make_ulonglong2(aL1, aH1);
        } else {
            const int r = tid - 96;
            float acc = sScb[r];
            #pragma unroll
            for (int j4 = 0; j4 < 8; j4++) {
                const float4 cr = *(const float4*)(sCb + r * 36 + j4 * 4);
                const float4 zz = *(const float4*)(sScb + 32 + j4 * 4);
                acc -= cr.x * zz.x + cr.y * zz.y + cr.z * zz.z + cr.w * zz.w;
            }
            #pragma unroll
            for (int j = 0; j < 24; j++) acc += sAB[j * 36 + r] * sv[j];
            sQ[r] = acc;
        }
        __syncthreads();

        // ---- stage B1: Quu + Qux only (15 tiles, 60 thr, 1x4, dup-AB loads)
        if (tid < 60) {
            const int r = b1_r, k0 = b1_k0;
            const ulonglong2 c2 = *(const ulonglong2*)(sCb + r * 36 + k0);
            ull aL = c2.x, aH = c2.y;
            #pragma unroll
            for (int j = 0; j < 24; j++) {
                const ull ar = *(const ull*)(sABd + j * 64 + 2 * r);
                const ulonglong2 gg = *(const ulonglong2*)(sG + j * 36 + k0);
                ffma2(aL, ar, gg.x); ffma2(aH, ar, gg.y);
            }
            const float2 lo = unpack2(aL), hi = unpack2(aH);
            float v[4] = { lo.x, lo.y, hi.x, hi.y };
            const int d = r - k0;
            if (d >= 0 && d < 4) v[d] += REGU;
            *(float4*)(sH + r * 36 + k0) = make_float4(v[0], v[1], v[2], v[3]);
        }
        __syncthreads();

        // ---- stage C: warp0 augmented GJ [Quu|Qux|Qu] -> K, kv
        //      threads 32..73: Qxx (21 lower tiles, 2x4, dup-AB loads)
        if (tid < 32) {
            const int seg = tid >> 3, r = tid & 7;
            float m[9];
            if (seg == 0) {
                #pragma unroll
                for (int j = 0; j < 8; j++)
                    m[j] = (j <= r) ? sH[(24 + r) * 36 + 24 + j]
                                    : sH[(24 + j) * 36 + 24 + r];
                m[8] = sQ[24 + r];
            } else {
                const int cb = (seg - 1) * 8;
                #pragma unroll
                for (int j = 0; j < 8; j++)
                    m[j] = sH[(24 + r) * 36 + cb + j];
                m[8] = 0.f;
            }
            #pragma unroll
            for (int cc = 0; cc < 8; cc++) {
                const float p   = __shfl_sync(0xffffffffu, m[cc], cc);
                const float inv = __fdividef(1.0f, p);
                const float f   = __shfl_sync(0xffffffffu, m[cc], r);
                const float fi  = f * inv;
                const int src = (seg << 3) | cc;
                float pr[9];
                #pragma unroll
                for (int j = 0; j < 9; j++) pr[j] = __shfl_sync(0xffffffffu, m[j], src);
                const bool isPiv = (r == cc);
                #pragma unroll
                for (int j = 0; j < 9; j++)
                    m[j] = isPiv ? (m[j] * inv) : (m[j] - fi * pr[j]);
            }
            if (seg == 0) {
                skv[r] = -m[8];
            } else {
                const int cb = (seg - 1) * 8;
                *(float4*)(sK + r * 28 + cb)     = make_float4(-m[0], -m[1], -m[2], -m[3]);
                *(float4*)(sK + r * 28 + cb + 4) = make_float4(-m[4], -m[5], -m[6], -m[7]);
            }
        } else if (tid < 74) {
            const int r0 = c_bi * 4 + ((tid - 32) & 1) * 2;
            const int k0 = c_bk * 4;
            const ulonglong2 c0 = *(const ulonglong2*)(sCb + r0 * 36 + k0);
            const ulonglong2 c1 = *(const ulonglong2*)(sCb + (r0 + 1) * 36 + k0);
            ull aL0 = c0.x, aH0 = c0.y, aL1 = c1.x, aH1 = c1.y;
            #pragma unroll
            for (int j = 0; j < 24; j++) {
                const ulonglong2 aa2 = *(const ulonglong2*)(sABd + j * 64 + 2 * r0); // (a0,a0,a1,a1)
                const ulonglong2 gg = *(const ulonglong2*)(sG + j * 36 + k0);
                ffma2(aL0, aa2.x, gg.x); ffma2(aH0, aa2.x, gg.y);
                ffma2(aL1, aa2.y, gg.x); ffma2(aH1, aa2.y, gg.y);
            }
            *(ulonglong2*)(sH + r0 * 36 + k0)       = make_ulonglong2(aL0, aH0);
            *(ulonglong2*)(sH + (r0 + 1) * 36 + k0) = make_ulonglong2(aL1, aH1);
        }
        __syncthreads();

        // ---- stage E: V tiles -> dup layout (0..41) ; g_K spill (74..89) ;
        //      g_kv (90..97) ; vn (100..123)
        if (tid < 42) {
            const int i0 = 4 * e_ti, k0 = 4 * e_tk;
            const int rh = i0 + (tid & 1) * 2;
            ull sL0 = 0, sH0 = 0, sL1 = 0, sH1 = 0;
            #pragma unroll
            for (int a = 0; a < 8; a++) {
                const float2 hi = *(const float2*)(sH + (24 + a) * 36 + rh);
                const ulonglong2 kk = *(const ulonglong2*)(sK + a * 28 + k0);
                const ull h0 = pack2(hi.x), h1 = pack2(hi.y);
                ffma2(sL0, h0, kk.x); ffma2(sH0, h0, kk.y);
                ffma2(sL1, h1, kk.x); ffma2(sH1, h1, kk.y);
            }
            const float2 s0a = unpack2(sL0), s0b = unpack2(sH0);
            const float2 s1a = unpack2(sL1), s1b = unpack2(sH1);
            const float S0[4] = { s0a.x, s0a.y, s0b.x, s0b.y };
            const float S1[4] = { s1a.x, s1a.y, s1b.x, s1b.y };
            const float4 h40 = *(const float4*)(sH + rh * 36 + k0);
            const float4 h41 = *(const float4*)(sH + (rh + 1) * 36 + k0);
            float v0[4], v1[4];
            #pragma unroll
            for (int c = 0; c < 4; c++) {
                v0[c] = (&h40.x)[c] + S0[c];
                v1[c] = (&h41.x)[c] + S1[c];
            }
            // duplicated row writes
            *(float4*)(sVd + rh * 48 + 2 * k0)     = make_float4(v0[0], v0[0], v0[1], v0[1]);
            *(float4*)(sVd + rh * 48 + 2 * k0 + 4) = make_float4(v0[2], v0[2], v0[3], v0[3]);
            *(float4*)(sVd + (rh + 1) * 48 + 2 * k0)     = make_float4(v1[0], v1[0], v1[1], v1[1]);
            *(float4*)(sVd + (rh + 1) * 48 + 2 * k0 + 4) = make_float4(v1[2], v1[2], v1[3], v1[3]);
            if (e_ti != e_tk) {
                #pragma unroll
                for (int c = 0; c < 4; c++)
                    *(float4*)(sVd + (k0 + c) * 48 + 2 * rh) =
                        make_float4(v0[c], v0[c], v1[c], v1[c]);
            }
        } else if (tid >= 74 && tid < 90) {
            const int i = tid - 74;
            const int row = i >> 1, cb = (i & 1) * 12;
            const float4 a0 = *(const float4*)(sK + row * 28 + cb);
            const float4 a1 = *(const float4*)(sK + row * 28 + cb + 4);
            const float4 a2 = *(const float4*)(sK + row * 28 + cb + 8);
            float* gk = g_K + (size_t)(b * T_HOR + t) * 192 + row * 24 + cb;
            *(float4*)(gk)     = a0;
            *(float4*)(gk + 4) = a1;
            *(float4*)(gk + 8) = a2;
        } else if (tid >= 90 && tid < 98) {
            g_kv[(size_t)(b * T_HOR + t) * 8 + (tid - 90)] = skv[tid - 90];
        } else if (tid >= 100 && tid < 124) {
            const int i = tid - 100;
            float acc = sQ[i];
            #pragma unroll
            for (int a = 0; a < 8; a++) acc += sH[(24 + a) * 36 + i] * skv[a];
            sv[i] = acc;
        }
        if (t > 0) asm volatile("cp.async.wait_group 0;" ::: "memory");
        __syncthreads();
        buf ^= 1;
    }

    // ---------------- forward rollout: warp 0 only ----------------
    if (tid >= 32) return;
    const int lane = tid;
    float* ob = d_out + (size_t)b * 3224;

    float* sAB2 = sG;  // bank-conflict-free [A|B]: stride 33
    for (int e = lane; e < 768; e += 32) {
        const int i = e >> 5, c = e & 31;
        sAB2[i * 33 + c] = sAB[i * 36 + c];
    }
    if (lane < 24) {
        const float xi = d_x0[b * 24 + lane];
        sx[lane] = xi;
        ob[lane] = xi;
    }
    float kc[24], kn[24], kvc = 0.f, kvn = 0.f;
    if (lane < 8) {
        const float* gk = g_K + (size_t)b * T_HOR * 192 + lane * 24;
        #pragma unroll
        for (int q = 0; q < 6; q++) {
            const float4 v = *(const float4*)(gk + q * 4);
            kc[q * 4 + 0] = v.x; kc[q * 4 + 1] = v.y;
            kc[q * 4 + 2] = v.z; kc[q * 4 + 3] = v.w;
        }
        kvc = g_kv[(size_t)b * T_HOR * 8 + lane];
    }
    __syncwarp();

    for (int t = 0; t < T_HOR; t++) {
        if (lane < 8 && t + 1 < T_HOR) {
            const float* gk = g_K + (size_t)(b * T_HOR + t + 1) * 192 + lane * 24;
            #pragma unroll
            for (int q = 0; q < 6; q++) {
                const float4 v = *(const float4*)(gk + q * 4);
                kn[q * 4 + 0] = v.x; kn[q * 4 + 1] = v.y;
                kn[q * 4 + 2] = v.z; kn[q * 4 + 3] = v.w;
            }
            kvn = g_kv[(size_t)(b * T_HOR + t + 1) * 8 + lane];
        }
        // u = K x + kv (lanes 0..7, two partial chains)
        float u = 0.f;
        if (lane < 8) {
            float u0 = kvc, u1 = 0.f;
            #pragma unroll
            for (int j = 0; j < 12; j++) {
                u0 += kc[j] * sx[j];
                u1 += kc[j + 12] * sx[j + 12];
            }
            u = u0 + u1;
            ob[2424 + t * 8 + lane] = u;
        }
        // broadcast u, x' = A x + B u (lanes 0..23, four partial chains)
        float acc = 0.f;
        {
            float ua[8];
            #pragma unroll
            for (int a = 0; a < 8; a++) ua[a] = __shfl_sync(0xffffffffu, u, a);
            if (lane < 24) {
                float a0 = 0.f, a1 = 0.f, a2 = 0.f, a3 = 0.f;
                #pragma unroll
                for (int j = 0; j < 8; j++) {
                    a0 += sAB2[lane * 33 + j]      * sx[j];
                    a1 += sAB2[lane * 33 + 8 + j]  * sx[8 + j];
                    a2 += sAB2[lane * 33 + 16 + j] * sx[16 + j];
                    a3 += sAB2[lane * 33 + 24 + j] * ua[j];
                }
                acc = (a0 + a1) + (a2 + a3);
            }
        }
        __syncwarp();
        if (lane < 24) {
            sx[lane] = acc;
            ob[(t + 1) * 24 + lane] = acc;
        }
        if (lane < 8) {
            #pragma unroll
            for (int q = 0; q < 24; q++) kc[q] = kn[q];
            kvc = kvn;
        }
        __syncwarp();
    }
}

extern "C" void kernel_launch(void* const* d_in, const int* in_sizes, int n_in,
                              void* d_out, int out_size)
{
    const float* x0   = (const float*)d_in[0];
    const float* C    = (const float*)d_in[1];
    const float* c    = (const float*)d_in[2];
    const float* Cf   = (const float*)d_in[3];
    const float* cf   = (const float*)d_in[4];
    const float* xref = (const float*)d_in[5];
    const float* uref = (const float*)d_in[6];
    const float* A    = (const float*)d_in[7];
    const float* B    = (const float*)d_in[8];

    lqr_kernel<<<B_BATCH, 128>>>(x0, C, c, Cf, cf, xref, uref, A, B, (float*)d_out);
}